// round 1
// baseline (speedup 1.0000x reference)
#include <cuda_runtime.h>

#define BB_ 32
#define HH_ 12
#define CC_ 512
#define DD_ 768
#define MM_ 8
#define EMB_ 768
#define NER_ 6
#define NCLS_ 97
#define KIN_ 1542
#define KCORE_ 1536

// ---------------- scratch (device globals; no allocation) ----------------
__device__ float g_hs[BB_ * DD_];          // logsumexp head embedding (b,d)
__device__ float g_htp[BB_ * CC_];         // pre-normalized ht_att (b,c)
__device__ float g_htsum[BB_ * 4];         // 4 partial sums per batch
__device__ float g_rsp[8 * BB_ * DD_];     // rs partials over 8 c-chunks (scaled by 1/denom)
__device__ float g_gp[2 * 12 * EMB_ * BB_];// GEMM partials [side][ks][n][b]
__device__ float g_hsf[BB_ * EMB_];        // tanh head features (b-major)
__device__ float g_tsf[BB_ * EMB_];        // tanh tail features
__device__ float g_lp[24 * BB_ * NCLS_];   // logits partials [ks][b][n]

// ---------------- f32x2 helpers (Blackwell packed fp32) ----------------
__device__ __forceinline__ unsigned long long ffma2(unsigned long long a,
                                                    unsigned long long b,
                                                    unsigned long long c) {
    unsigned long long d;
    asm("fma.rn.f32x2 %0, %1, %2, %3;" : "=l"(d) : "l"(a), "l"(b), "l"(c));
    return d;
}
__device__ __forceinline__ unsigned long long pack2(float x) {
    unsigned long long r;
    asm("mov.b64 %0, {%1, %2};" : "=l"(r) : "f"(x), "f"(x));
    return r;
}
__device__ __forceinline__ float2 unpack2(unsigned long long v) {
    float2 f;
    asm("mov.b64 {%0, %1}, %2;" : "=f"(f.x), "=f"(f.y) : "l"(v));
    return f;
}

// ================= K1: hs (logsumexp) + ht_att pre + partial sums =================
// grid (4, 32): x = quarter, y = batch. 192 threads.
__global__ __launch_bounds__(192) void k1(const float* __restrict__ seq,
                                          const float* __restrict__ att,
                                          const int* __restrict__ ep) {
    int part = blockIdx.x, b = blockIdx.y, tid = threadIdx.x;
    __shared__ int sp0[8], sp1[8];
    __shared__ float sred[6];
    if (tid < 16) {
        int side = tid >> 3, m = tid & 7;
        int p = ep[b * 16 + side * 8 + m] + 1;  // OFFSET
        if (side) sp1[m] = p; else sp0[m] = p;
    }
    __syncthreads();

    // --- hs: logsumexp over 8 gathered rows, one d per thread ---
    {
        int d = part * 192 + tid;  // 4*192 = 768 exactly
        const float* sb = seq + b * CC_ * DD_ + d;
        float v[8];
        #pragma unroll
        for (int m = 0; m < 8; m++) v[m] = sb[sp0[m] * DD_];
        float mx = v[0];
        #pragma unroll
        for (int m = 1; m < 8; m++) mx = fmaxf(mx, v[m]);
        float s = 0.f;
        #pragma unroll
        for (int m = 0; m < 8; m++) s += expf(v[m] - mx);
        g_hs[b * DD_ + d] = mx + logf(s);
    }

    // --- ht_att pre-normalization: one c per thread (first 128 threads) ---
    float pre = 0.f;
    if (tid < 128) {
        int c = part * 128 + tid;
        const float* ab = att + (size_t)b * HH_ * CC_ * CC_ + c;
        float acc = 0.f;
        #pragma unroll
        for (int h = 0; h < HH_; h++) {
            const float* ah = ab + (size_t)h * CC_ * CC_;
            float a0 = 0.f, a1 = 0.f;
            #pragma unroll
            for (int m = 0; m < 8; m++) {
                a0 += ah[sp0[m] * CC_];
                a1 += ah[sp1[m] * CC_];
            }
            acc += a0 * a1;
        }
        pre = acc * (1.0f / 768.0f);   // /(M*M*H) = /(8*8*12)
        g_htp[b * CC_ + c] = pre;
    }
    // block partial sum of pre
    #pragma unroll
    for (int o = 16; o > 0; o >>= 1) pre += __shfl_xor_sync(0xffffffffu, pre, o);
    if ((tid & 31) == 0) sred[tid >> 5] = pre;
    __syncthreads();
    if (tid == 0)
        g_htsum[b * 4 + part] = sred[0] + sred[1] + sred[2] + sred[3];
}

// ================= K2: rs partials, 50MB streaming read =================
// grid (8, 32): x = c-chunk (64 rows), y = batch. 192 threads (float4 over 768 d).
__global__ __launch_bounds__(192) void k2(const float* __restrict__ seq) {
    int s = blockIdx.x, b = blockIdx.y, tid = threadIdx.x;
    __shared__ float sht[64];
    __shared__ float sinv;
    if (tid == 0) {
        float sm = g_htsum[b * 4] + g_htsum[b * 4 + 1] + g_htsum[b * 4 + 2] + g_htsum[b * 4 + 3];
        sinv = 1.0f / (sm + 1e-5f);
    }
    if (tid < 64) sht[tid] = g_htp[b * CC_ + s * 64 + tid];
    __syncthreads();

    const float4* sp = (const float4*)(seq + (b * CC_ + s * 64) * DD_);
    float4 acc = make_float4(0.f, 0.f, 0.f, 0.f);
    #pragma unroll 4
    for (int cc = 0; cc < 64; cc++) {
        float w = sht[cc];
        float4 v = sp[cc * 192 + tid];
        acc.x += v.x * w; acc.y += v.y * w; acc.z += v.z * w; acc.w += v.w * w;
    }
    float iv = sinv;
    acc.x *= iv; acc.y *= iv; acc.z *= iv; acc.w *= iv;
    ((float4*)(g_rsp + (s * BB_ + b) * DD_))[tid] = acc;
}

// ================= K3: dual GEMM partials (head/tail), f32x2 =================
// grid (6, 12, 2): x = n-tile(128), y = k-split(128, covers k<1536), z = side.
// 128 threads: tx(16) x ty(8). Thread tile: 8 n x 4 b (b packed in f32x2 pairs).
__global__ __launch_bounds__(128) void k3(const float* __restrict__ Wh,
                                          const float* __restrict__ Wt) {
    int nt = blockIdx.x, ks = blockIdx.y, side = blockIdx.z;
    int tid = threadIdx.x, tx = tid & 15, ty = tid >> 4;
    const float* W = side ? Wt : Wh;
    int n0 = nt * 128, k0 = ks * 128;

    __shared__ float w_s[64][129];                 // [kk][n], padded stride
    __shared__ __align__(16) float x_s[64][32];    // [kk][b]

    unsigned long long acc[8][2];
    #pragma unroll
    for (int i = 0; i < 8; i++) { acc[i][0] = 0ull; acc[i][1] = 0ull; }

    for (int ch = 0; ch < 2; ch++) {
        int kb = k0 + ch * 64;
        // stage W tile: 64k x 128n
        for (int idx = tid; idx < 8192; idx += 128) {
            int n = idx >> 6, kk = idx & 63;
            w_s[kk][n] = W[(n0 + n) * KIN_ + kb + kk];
        }
        // stage x tile: 64k x 32b (hs for k<768, summed rs partials otherwise)
        for (int idx = tid; idx < 2048; idx += 128) {
            int kk = idx >> 5, bb = idx & 31;
            int gk = kb + kk;
            float v;
            if (gk < 768) {
                v = g_hs[bb * DD_ + gk];
            } else {
                int g2 = gk - 768;
                v = 0.f;
                #pragma unroll
                for (int s2 = 0; s2 < 8; s2++) v += g_rsp[(s2 * BB_ + bb) * DD_ + g2];
            }
            x_s[kk][bb] = v;
        }
        __syncthreads();
        #pragma unroll 4
        for (int kk = 0; kk < 64; kk++) {
            unsigned long long xa0 = *(const unsigned long long*)&x_s[kk][ty * 4];
            unsigned long long xa1 = *(const unsigned long long*)&x_s[kk][ty * 4 + 2];
            #pragma unroll
            for (int i = 0; i < 8; i++) {
                unsigned long long w2 = pack2(w_s[kk][tx + (i << 4)]);
                acc[i][0] = ffma2(w2, xa0, acc[i][0]);
                acc[i][1] = ffma2(w2, xa1, acc[i][1]);
            }
        }
        __syncthreads();
    }
    float* gp = g_gp + (size_t)(side * 12 + ks) * EMB_ * BB_;
    #pragma unroll
    for (int i = 0; i < 8; i++) {
        int n = n0 + tx + (i << 4);
        #pragma unroll
        for (int p = 0; p < 2; p++) {
            float2 v = unpack2(acc[i][p]);
            int bb = ty * 4 + p * 2;
            *(float2*)(gp + n * BB_ + bb) = v;
        }
    }
}

// ================= K3r: reduce k-partials + NER tail + bias + tanh =================
// grid (192), 256 threads: 49152 outputs (2 sides x 768 n x 32 b).
__global__ __launch_bounds__(256) void k3r(const float* __restrict__ Wh,
                                           const float* __restrict__ Wt,
                                           const float* __restrict__ bh,
                                           const float* __restrict__ bt,
                                           const float* __restrict__ ner) {
    int gid = blockIdx.x * 256 + threadIdx.x;
    int side = gid >= (EMB_ * BB_);
    int loc = side ? gid - EMB_ * BB_ : gid;
    int n = loc >> 5, bb = loc & 31;
    const float* gp = g_gp + (size_t)side * 12 * EMB_ * BB_ + n * BB_ + bb;
    float s = 0.f;
    #pragma unroll
    for (int ks = 0; ks < 12; ks++) s += gp[(size_t)ks * EMB_ * BB_];
    const float* W = side ? Wt : Wh;
    #pragma unroll
    for (int j = 0; j < 6; j++)
        s += W[n * KIN_ + KCORE_ + j] * ner[bb * 12 + side * 6 + j];
    s += (side ? bt : bh)[n];
    float v = tanhf(s);
    (side ? g_tsf : g_hsf)[bb * EMB_ + n] = v;
}

// ================= K4: bilinear + logits GEMM partials, f32x2 =================
// grid (4, 24): x = n-tile(32), y = k-split(256 of 6144). 128 threads: tx(16) x ty(8).
// Thread tile: 2 n x 4 b. bl computed on the fly into smem.
__global__ __launch_bounds__(128) void k4(const float* __restrict__ Wb) {
    int nt = blockIdx.x, ks = blockIdx.y;
    int tid = threadIdx.x, tx = tid & 15, ty = tid >> 4;
    int n0 = nt * 32;

    __shared__ float sh[32][33], st[32][33];       // [b][v], padded
    __shared__ float w_s[64][33];                  // [kk][n], padded
    __shared__ __align__(16) float x_s[64][32];    // bl chunk [kk][b]

    for (int idx = tid; idx < 1024; idx += 128) {
        int bb = idx >> 5, v = idx & 31;
        sh[bb][v] = g_hsf[bb * EMB_ + ks * 32 + v];
        st[bb][v] = g_tsf[bb * EMB_ + ks * 32 + v];
    }
    __syncthreads();

    unsigned long long acc[2][2] = {{0ull, 0ull}, {0ull, 0ull}};
    for (int ch = 0; ch < 4; ch++) {
        int kc = ch * 64;
        for (int idx = tid; idx < 2048; idx += 128) {
            int n = idx >> 6, kk = idx & 63;
            int nn = n0 + n;
            w_s[kk][n] = (nn < NCLS_) ? Wb[nn * 6144 + ks * 256 + kc + kk] : 0.f;
        }
        for (int idx = tid; idx < 2048; idx += 128) {
            int kk = idx >> 5, bb = idx & 31;
            int kl = kc + kk;
            int g = kl >> 6, i = (kl >> 3) & 7, j = kl & 7;
            x_s[kk][bb] = sh[bb][g * 8 + i] * st[bb][g * 8 + j];
        }
        __syncthreads();
        #pragma unroll 4
        for (int kk = 0; kk < 64; kk++) {
            unsigned long long xa0 = *(const unsigned long long*)&x_s[kk][ty * 4];
            unsigned long long xa1 = *(const unsigned long long*)&x_s[kk][ty * 4 + 2];
            #pragma unroll
            for (int i = 0; i < 2; i++) {
                unsigned long long w2 = pack2(w_s[kk][tx + (i << 4)]);
                acc[i][0] = ffma2(w2, xa0, acc[i][0]);
                acc[i][1] = ffma2(w2, xa1, acc[i][1]);
            }
        }
        __syncthreads();
    }
    float* lp = g_lp + ks * BB_ * NCLS_;
    #pragma unroll
    for (int i = 0; i < 2; i++) {
        int n = n0 + tx + (i << 4);
        if (n < NCLS_) {
            #pragma unroll
            for (int p = 0; p < 2; p++) {
                float2 v = unpack2(acc[i][p]);
                int bb = ty * 4 + p * 2;
                lp[bb * NCLS_ + n] = v.x;
                lp[(bb + 1) * NCLS_ + n] = v.y;
            }
        }
    }
}

// ================= K5: final reduce + bias -> d_out =================
__global__ __launch_bounds__(256) void k5(const float* __restrict__ bbil,
                                          float* __restrict__ out) {
    int gid = blockIdx.x * 256 + threadIdx.x;
    if (gid < BB_ * NCLS_) {
        int n = gid % NCLS_;
        float s = bbil[n];
        #pragma unroll
        for (int ks = 0; ks < 24; ks++) s += g_lp[ks * BB_ * NCLS_ + gid];
        out[gid] = s;
    }
}

extern "C" void kernel_launch(void* const* d_in, const int* in_sizes, int n_in,
                              void* d_out, int out_size) {
    const float* seq  = (const float*)d_in[0];
    const float* att  = (const float*)d_in[1];
    const float* ner  = (const float*)d_in[2];
    const float* Wh   = (const float*)d_in[3];
    const float* bh   = (const float*)d_in[4];
    const float* Wt   = (const float*)d_in[5];
    const float* bt   = (const float*)d_in[6];
    const float* Wb   = (const float*)d_in[7];
    const float* bbil = (const float*)d_in[8];
    const int*   ep   = (const int*)d_in[9];
    float* out = (float*)d_out;

    k1<<<dim3(4, 32), 192>>>(seq, att, ep);
    k2<<<dim3(8, 32), 192>>>(seq);
    k3<<<dim3(6, 12, 2), 128>>>(Wh, Wt);
    k3r<<<192, 256>>>(Wh, Wt, bh, bt, ner);
    k4<<<dim3(4, 24), 128>>>(Wb);
    k5<<<13, 256>>>(bbil, out);
}

// round 2
// speedup vs baseline: 1.2969x; 1.2969x over previous
#include <cuda_runtime.h>

#define BB_ 32
#define HH_ 12
#define CC_ 512
#define DD_ 768
#define EMB_ 768
#define NER_ 6
#define NCLS_ 97
#define KIN_ 1542
#define KCORE_ 1536

// ---------------- scratch (device globals; no allocation) ----------------
__device__ float g_hs[BB_ * DD_];                       // logsumexp head emb (b,d)
__device__ float g_htp[BB_ * CC_];                      // pre-normalized ht_att (b,c)
__device__ float g_htsum[BB_ * 4];                      // 4 partial sums per batch
__device__ float g_rsp[4 * BB_ * DD_];                  // rs partials (4 c-chunks)
__device__ unsigned long long g_gpu[2 * 24 * 384 * 32]; // GEMM partials [side][ks][P][b] (n-pairs)
__device__ float g_hsf[BB_ * EMB_];                     // tanh head features [b][n]
__device__ float g_tsf[BB_ * EMB_];                     // tanh tail features [b][n]
__device__ unsigned long long g_lp2[24 * 64 * 32];      // logits partials [ks][P][b] (n-pairs)

// ---------------- f32x2 helpers ----------------
__device__ __forceinline__ unsigned long long ffma2(unsigned long long a,
                                                    unsigned long long b,
                                                    unsigned long long c) {
    unsigned long long d;
    asm("fma.rn.f32x2 %0, %1, %2, %3;" : "=l"(d) : "l"(a), "l"(b), "l"(c));
    return d;
}
__device__ __forceinline__ unsigned long long addf2(unsigned long long a,
                                                    unsigned long long b) {
    unsigned long long d;
    asm("add.rn.f32x2 %0, %1, %2;" : "=l"(d) : "l"(a), "l"(b));
    return d;
}
__device__ __forceinline__ unsigned long long pack2(float x) {
    unsigned long long r;
    asm("mov.b64 %0, {%1, %2};" : "=l"(r) : "f"(x), "f"(x));
    return r;
}
__device__ __forceinline__ float2 unpack2(unsigned long long v) {
    float2 f;
    asm("mov.b64 {%0, %1}, %2;" : "=f"(f.x), "=f"(f.y) : "l"(v));
    return f;
}

// ================= K1: hs (logsumexp) + ht_att pre + partial sums =================
// grid (4, 32): x = c-quarter, y = batch. 384 threads = 12 warps (warp = head).
__global__ __launch_bounds__(384) void k1(const float* __restrict__ seq,
                                          const float* __restrict__ att,
                                          const int* __restrict__ ep) {
    int part = blockIdx.x, b = blockIdx.y, tid = threadIdx.x;
    int w = tid >> 5, lane = tid & 31;
    __shared__ int sp0[8], sp1[8];
    __shared__ float sacc[12][128];
    __shared__ float sred[12];
    if (tid < 16) {
        int side = tid >> 3, m = tid & 7;
        int p = ep[b * 16 + side * 8 + m] + 1;  // OFFSET
        if (side) sp1[m] = p; else sp0[m] = p;
    }
    __syncthreads();

    // --- attention gather: warp w handles head h=w, lane owns 4 consecutive c ---
    {
        const float* ab = att + ((size_t)(b * HH_ + w)) * CC_ * CC_;
        int c4 = part * 128 + lane * 4;
        float4 a0 = make_float4(0.f, 0.f, 0.f, 0.f);
        float4 a1 = make_float4(0.f, 0.f, 0.f, 0.f);
        #pragma unroll
        for (int m = 0; m < 8; m++) {
            float4 v0 = *(const float4*)(ab + (size_t)sp0[m] * CC_ + c4);
            float4 v1 = *(const float4*)(ab + (size_t)sp1[m] * CC_ + c4);
            a0.x += v0.x; a0.y += v0.y; a0.z += v0.z; a0.w += v0.w;
            a1.x += v1.x; a1.y += v1.y; a1.z += v1.z; a1.w += v1.w;
        }
        float4 pr = make_float4(a0.x * a1.x, a0.y * a1.y, a0.z * a1.z, a0.w * a1.w);
        *(float4*)&sacc[w][lane * 4] = pr;
    }
    __syncthreads();

    // --- reduce over heads for 128 c's, write g_htp, block-sum to g_htsum ---
    float pre = 0.f;
    if (tid < 128) {
        float s = 0.f;
        #pragma unroll
        for (int h = 0; h < 12; h++) s += sacc[h][tid];
        pre = s * (1.0f / 768.0f);   // /(M*M*H)
        g_htp[b * CC_ + part * 128 + tid] = pre;
    }
    #pragma unroll
    for (int o = 16; o > 0; o >>= 1) pre += __shfl_xor_sync(0xffffffffu, pre, o);
    if (lane == 0) sred[w] = pre;
    __syncthreads();
    if (tid == 0) {
        float s = 0.f;
        #pragma unroll
        for (int i = 0; i < 12; i++) s += sred[i];
        g_htsum[b * 4 + part] = s;
    }

    // --- hs logsumexp: parts 0,1 cover 768 d ---
    if (part < 2) {
        int d = part * 384 + tid;
        const float* sb = seq + (size_t)b * CC_ * DD_ + d;
        float v[8];
        #pragma unroll
        for (int m = 0; m < 8; m++) v[m] = sb[(size_t)sp0[m] * DD_];
        float mx = v[0];
        #pragma unroll
        for (int m = 1; m < 8; m++) mx = fmaxf(mx, v[m]);
        float s = 0.f;
        #pragma unroll
        for (int m = 0; m < 8; m++) s += expf(v[m] - mx);
        g_hs[b * DD_ + d] = mx + logf(s);
    }
}

// ================= K2: rs partials (50MB streaming read) =================
// grid (4, 32): x = c-chunk (128 rows), y = batch. 192 threads, float4, unroll 8.
__global__ __launch_bounds__(192) void k2(const float* __restrict__ seq) {
    int s = blockIdx.x, b = blockIdx.y, tid = threadIdx.x;
    __shared__ float sht[128];
    __shared__ float sinv;
    if (tid == 0) {
        float sm = g_htsum[b * 4] + g_htsum[b * 4 + 1] + g_htsum[b * 4 + 2] + g_htsum[b * 4 + 3];
        sinv = 1.0f / (sm + 1e-5f);
    }
    if (tid < 128) sht[tid] = g_htp[b * CC_ + s * 128 + tid];
    __syncthreads();

    const float4* sp = (const float4*)(seq + ((size_t)b * CC_ + s * 128) * DD_);
    float4 acc = make_float4(0.f, 0.f, 0.f, 0.f);
    #pragma unroll 8
    for (int cc = 0; cc < 128; cc++) {
        float wv = sht[cc];
        float4 v = sp[cc * 192 + tid];
        acc.x += v.x * wv; acc.y += v.y * wv; acc.z += v.z * wv; acc.w += v.w * wv;
    }
    float iv = sinv;
    acc.x *= iv; acc.y *= iv; acc.z *= iv; acc.w *= iv;
    ((float4*)(g_rsp + ((size_t)s * BB_ + b) * DD_))[tid] = acc;
}

// ================= K3: dual GEMM partials (head/tail), f32x2, x2-broadcast =================
// grid (8, 24, 2): x = n-tile(96), y = k-split(64), z = side. 128 threads tx(16)xty(8).
// Thread tile: 3 n-pairs (6 n) x 4 b.
__global__ __launch_bounds__(128) void k3(const float* __restrict__ Wh,
                                          const float* __restrict__ Wt) {
    int nt = blockIdx.x, ks = blockIdx.y, side = blockIdx.z;
    int tid = threadIdx.x, tx = tid & 15, ty = tid >> 4;
    const float* W = side ? Wt : Wh;
    int n0 = nt * 96, kb = ks * 64;

    __shared__ float w_s[64][98];                        // [kk][n], stride even for LDS.64
    __shared__ unsigned long long x2_s[64][32];          // packed-duplicate x [kk][b]

    // stage W tile 64k x 96n via float2 along k (fully unrolled -> MLP 24)
    #pragma unroll
    for (int t = 0; t < 24; t++) {
        int idx = tid + t * 128;          // 0..3071
        int n = idx >> 5;                 // 0..95
        int kq = idx & 31;                // float2 idx -> kk = 2*kq
        float2 v = *(const float2*)(W + (size_t)(n0 + n) * KIN_ + kb + kq * 2);
        w_s[kq * 2][n] = v.x;
        w_s[kq * 2 + 1][n] = v.y;
    }
    // stage x2: 2048 elems, 16/thread
    #pragma unroll
    for (int t = 0; t < 16; t++) {
        int idx = tid + t * 128;
        int kk = idx >> 5, bb = idx & 31;
        int gk = kb + kk;
        float v;
        if (gk < 768) {
            v = g_hs[bb * DD_ + gk];
        } else {
            int g2 = gk - 768;
            v = g_rsp[(0 * BB_ + bb) * DD_ + g2] + g_rsp[(1 * BB_ + bb) * DD_ + g2]
              + g_rsp[(2 * BB_ + bb) * DD_ + g2] + g_rsp[(3 * BB_ + bb) * DD_ + g2];
        }
        x2_s[kk][bb] = pack2(v);
    }
    __syncthreads();

    unsigned long long acc[3][4];
    #pragma unroll
    for (int i = 0; i < 3; i++)
        #pragma unroll
        for (int j = 0; j < 4; j++) acc[i][j] = 0ull;

    #pragma unroll 2
    for (int kk = 0; kk < 64; kk++) {
        unsigned long long w2[3], xb[4];
        #pragma unroll
        for (int i = 0; i < 3; i++)
            w2[i] = *(const unsigned long long*)&w_s[kk][2 * (tx + 16 * i)];
        #pragma unroll
        for (int j = 0; j < 4; j++) xb[j] = x2_s[kk][ty * 4 + j];
        #pragma unroll
        for (int i = 0; i < 3; i++)
            #pragma unroll
            for (int j = 0; j < 4; j++) acc[i][j] = ffma2(w2[i], xb[j], acc[i][j]);
    }

    unsigned long long* gp = g_gpu + ((size_t)(side * 24 + ks)) * 384 * 32;
    #pragma unroll
    for (int i = 0; i < 3; i++) {
        int P = nt * 48 + tx + 16 * i;    // global n-pair
        #pragma unroll
        for (int j = 0; j < 4; j++)
            gp[P * 32 + ty * 4 + j] = acc[i][j];
    }
}

// ================= K3r: reduce 24 k-partials (f32x2) + NER + bias + tanh =================
// 24576 pair-outputs: grid 96 x 256.
__global__ __launch_bounds__(256) void k3r(const float* __restrict__ Wh,
                                           const float* __restrict__ Wt,
                                           const float* __restrict__ bh,
                                           const float* __restrict__ bt,
                                           const float* __restrict__ ner) {
    int gid = blockIdx.x * 256 + threadIdx.x;
    int side = gid / 12288;
    int rem = gid - side * 12288;
    int P = rem >> 5, bb = rem & 31;
    const unsigned long long* gp = g_gpu + (size_t)side * 24 * 384 * 32 + P * 32 + bb;
    unsigned long long s = 0ull;
    #pragma unroll
    for (int ks = 0; ks < 24; ks++) s = addf2(s, gp[(size_t)ks * 384 * 32]);
    float2 v = unpack2(s);
    const float* W = side ? Wt : Wh;
    int n = 2 * P;
    float s0 = v.x, s1 = v.y;
    #pragma unroll
    for (int j = 0; j < 6; j++) {
        float nv = ner[bb * 12 + side * 6 + j];
        s0 += W[(size_t)n * KIN_ + KCORE_ + j] * nv;
        s1 += W[(size_t)(n + 1) * KIN_ + KCORE_ + j] * nv;
    }
    const float* bias = side ? bt : bh;
    s0 += bias[n]; s1 += bias[n + 1];
    float* dst = side ? g_tsf : g_hsf;
    dst[bb * EMB_ + n] = tanhf(s0);
    dst[bb * EMB_ + n + 1] = tanhf(s1);
}

// ================= K4: bilinear + logits GEMM partials, f32x2 =================
// grid (4, 24): x = n-tile(32), y = k-split(256 = 4 groups of 64). 128 threads tx(16)xty(8).
__global__ __launch_bounds__(128) void k4(const float* __restrict__ Wb) {
    int nt = blockIdx.x, ks = blockIdx.y;
    int tid = threadIdx.x, tx = tid & 15, ty = tid >> 4;
    int n0 = nt * 32;

    __shared__ float sh[32][33], st[32][33];
    __shared__ float w_s[64][34];
    __shared__ unsigned long long x2_s[64][32];

    #pragma unroll
    for (int t = 0; t < 8; t++) {
        int idx = tid + t * 128;
        int bb = idx >> 5, v = idx & 31;
        sh[bb][v] = g_hsf[bb * EMB_ + ks * 32 + v];
        st[bb][v] = g_tsf[bb * EMB_ + ks * 32 + v];
    }
    __syncthreads();

    unsigned long long acc[4] = {0ull, 0ull, 0ull, 0ull};
    for (int ch = 0; ch < 4; ch++) {
        // stage W chunk 64k x 32n via float4 (row stride 6144 floats, 16B aligned)
        #pragma unroll
        for (int t = 0; t < 4; t++) {
            int idx = tid + t * 128;      // 0..511
            int n = idx >> 4;             // 0..31
            int kq = idx & 15;            // kk = 4*kq
            int nn = n0 + n;
            float4 v = (nn < NCLS_)
                ? *(const float4*)(Wb + (size_t)nn * 6144 + ks * 256 + ch * 64 + kq * 4)
                : make_float4(0.f, 0.f, 0.f, 0.f);
            w_s[kq * 4 + 0][n] = v.x;
            w_s[kq * 4 + 1][n] = v.y;
            w_s[kq * 4 + 2][n] = v.z;
            w_s[kq * 4 + 3][n] = v.w;
        }
        // bl chunk on-the-fly
        #pragma unroll
        for (int t = 0; t < 16; t++) {
            int idx = tid + t * 128;
            int kk = idx >> 5, bb = idx & 31;
            int i = kk >> 3, j = kk & 7;
            x2_s[kk][bb] = pack2(sh[bb][ch * 8 + i] * st[bb][ch * 8 + j]);
        }
        __syncthreads();
        #pragma unroll 4
        for (int kk = 0; kk < 64; kk++) {
            unsigned long long w2 = *(const unsigned long long*)&w_s[kk][2 * tx];
            #pragma unroll
            for (int j = 0; j < 4; j++)
                acc[j] = ffma2(w2, x2_s[kk][ty * 4 + j], acc[j]);
        }
        __syncthreads();
    }
    int P = nt * 16 + tx;   // global n-pair, 0..63
    #pragma unroll
    for (int j = 0; j < 4; j++)
        g_lp2[((size_t)ks * 64 + P) * 32 + ty * 4 + j] = acc[j];
}

// ================= K5: final reduce + bias -> d_out =================
__global__ __launch_bounds__(256) void k5(const float* __restrict__ bbil,
                                          float* __restrict__ out) {
    int gid = blockIdx.x * 256 + threadIdx.x;
    if (gid < BB_ * NCLS_) {
        int b = gid / NCLS_, n = gid - b * NCLS_;
        int P = n >> 1, c = n & 1;
        const float* lpf = (const float*)g_lp2;
        float s = bbil[n];
        #pragma unroll
        for (int ks = 0; ks < 24; ks++)
            s += lpf[(((size_t)ks * 64 + P) * 32 + b) * 2 + c];
        out[gid] = s;
    }
}

extern "C" void kernel_launch(void* const* d_in, const int* in_sizes, int n_in,
                              void* d_out, int out_size) {
    const float* seq  = (const float*)d_in[0];
    const float* att  = (const float*)d_in[1];
    const float* ner  = (const float*)d_in[2];
    const float* Wh   = (const float*)d_in[3];
    const float* bh   = (const float*)d_in[4];
    const float* Wt   = (const float*)d_in[5];
    const float* bt   = (const float*)d_in[6];
    const float* Wb   = (const float*)d_in[7];
    const float* bbil = (const float*)d_in[8];
    const int*   ep   = (const int*)d_in[9];
    float* out = (float*)d_out;

    k1<<<dim3(4, 32), 384>>>(seq, att, ep);
    k2<<<dim3(4, 32), 192>>>(seq);
    k3<<<dim3(8, 24, 2), 128>>>(Wh, Wt);
    k3r<<<96, 256>>>(Wh, Wt, bh, bt, ner);
    k4<<<dim3(4, 24), 128>>>(Wb);
    k5<<<13, 256>>>(bbil, out);
}

// round 3
// speedup vs baseline: 2.2068x; 1.7016x over previous
#include <cuda_runtime.h>

#define BB_ 32
#define HH_ 12
#define CC_ 512
#define DD_ 768
#define EMB_ 768
#define NCLS_ 97
#define KIN_ 1542
#define KCORE_ 1536

// ---------------- scratch (device globals; no allocation) ----------------
__device__ float g_hs_t[DD_ * BB_];                     // logsumexp head emb [d][b]
__device__ float g_htp[BB_ * CC_];                      // pre-normalized ht_att (b,c)
__device__ float g_htsum[BB_ * 4];                      // 4 partial sums per batch
__device__ float g_rsp[16 * BB_ * DD_];                 // rs partials [chunk][b][d]
__device__ float g_rs_t[DD_ * BB_];                     // reduced rs [d][b]
__device__ unsigned long long g_gpu[2 * 24 * 384 * 32]; // GEMM partials [side][ks][P][b]
__device__ float g_hsf_t[EMB_ * BB_];                   // tanh head features [n][b]
__device__ float g_tsf_t[EMB_ * BB_];                   // tanh tail features [n][b]
__device__ unsigned long long g_lp2[24 * 64 * 32];      // logits partials [ks][P][b]

// ---------------- f32x2 helpers ----------------
__device__ __forceinline__ unsigned long long ffma2(unsigned long long a,
                                                    unsigned long long b,
                                                    unsigned long long c) {
    unsigned long long d;
    asm("fma.rn.f32x2 %0, %1, %2, %3;" : "=l"(d) : "l"(a), "l"(b), "l"(c));
    return d;
}
__device__ __forceinline__ unsigned long long addf2(unsigned long long a,
                                                    unsigned long long b) {
    unsigned long long d;
    asm("add.rn.f32x2 %0, %1, %2;" : "=l"(d) : "l"(a), "l"(b));
    return d;
}
__device__ __forceinline__ unsigned long long pack2(float x) {
    unsigned long long r;
    asm("mov.b64 %0, {%1, %2};" : "=l"(r) : "f"(x), "f"(x));
    return r;
}
__device__ __forceinline__ float2 unpack2(unsigned long long v) {
    float2 f;
    asm("mov.b64 {%0, %1}, %2;" : "=f"(f.x), "=f"(f.y) : "l"(v));
    return f;
}

// ================= K1: hs (logsumexp) + ht_att pre + partial sums =================
// grid (4, 32): x = c-quarter, y = batch. 384 threads = 12 warps (warp = head).
__global__ __launch_bounds__(384) void k1(const float* __restrict__ seq,
                                          const float* __restrict__ att,
                                          const int* __restrict__ ep) {
    int part = blockIdx.x, b = blockIdx.y, tid = threadIdx.x;
    int w = tid >> 5, lane = tid & 31;
    __shared__ int sp0[8], sp1[8];
    __shared__ float sacc[12][128];
    __shared__ float sred[12];
    if (tid < 16) {
        int side = tid >> 3, m = tid & 7;
        int p = ep[b * 16 + side * 8 + m] + 1;  // OFFSET
        if (side) sp1[m] = p; else sp0[m] = p;
    }
    __syncthreads();

    // --- attention gather: warp w = head w, lane owns 4 consecutive c ---
    {
        const float* ab = att + ((size_t)(b * HH_ + w)) * CC_ * CC_;
        int c4 = part * 128 + lane * 4;
        float4 v0[8], v1[8];
        #pragma unroll
        for (int m = 0; m < 8; m++) {
            v0[m] = *(const float4*)(ab + (size_t)sp0[m] * CC_ + c4);
            v1[m] = *(const float4*)(ab + (size_t)sp1[m] * CC_ + c4);
        }
        float4 a0 = make_float4(0.f, 0.f, 0.f, 0.f);
        float4 a1 = make_float4(0.f, 0.f, 0.f, 0.f);
        #pragma unroll
        for (int m = 0; m < 8; m++) {
            a0.x += v0[m].x; a0.y += v0[m].y; a0.z += v0[m].z; a0.w += v0[m].w;
            a1.x += v1[m].x; a1.y += v1[m].y; a1.z += v1[m].z; a1.w += v1[m].w;
        }
        float4 pr = make_float4(a0.x * a1.x, a0.y * a1.y, a0.z * a1.z, a0.w * a1.w);
        *(float4*)&sacc[w][lane * 4] = pr;
    }
    __syncthreads();

    // --- reduce over heads, write g_htp + block partial sum ---
    float pre = 0.f;
    if (tid < 128) {
        float s = 0.f;
        #pragma unroll
        for (int h = 0; h < 12; h++) s += sacc[h][tid];
        pre = s * (1.0f / 768.0f);   // /(M*M*H)
        g_htp[b * CC_ + part * 128 + tid] = pre;
    }
    #pragma unroll
    for (int o = 16; o > 0; o >>= 1) pre += __shfl_xor_sync(0xffffffffu, pre, o);
    if (lane == 0) sred[w] = pre;
    __syncthreads();
    if (tid == 0) {
        float s = 0.f;
        #pragma unroll
        for (int i = 0; i < 12; i++) s += sred[i];
        g_htsum[b * 4 + part] = s;
    }

    // --- hs logsumexp: parts 0,1 cover 768 d; write transposed [d][b] ---
    if (part < 2) {
        int d = part * 384 + tid;
        const float* sb = seq + (size_t)b * CC_ * DD_ + d;
        float v[8];
        #pragma unroll
        for (int m = 0; m < 8; m++) v[m] = sb[(size_t)sp0[m] * DD_];
        float mx = v[0];
        #pragma unroll
        for (int m = 1; m < 8; m++) mx = fmaxf(mx, v[m]);
        float s = 0.f;
        #pragma unroll
        for (int m = 0; m < 8; m++) s += expf(v[m] - mx);
        g_hs_t[d * BB_ + b] = mx + logf(s);
    }
}

// ================= K2: rs partials (50MB streaming read), explicit MLP=8 =================
// grid (16, 32): x = c-chunk (32 rows), y = batch. 192 threads (float4 over d).
__global__ __launch_bounds__(192) void k2(const float* __restrict__ seq) {
    int s = blockIdx.x, b = blockIdx.y, tid = threadIdx.x;
    __shared__ float sht[32];
    __shared__ float sinv;
    if (tid == 0) {
        float sm = g_htsum[b * 4] + g_htsum[b * 4 + 1] + g_htsum[b * 4 + 2] + g_htsum[b * 4 + 3];
        sinv = 1.0f / (sm + 1e-5f);
    }
    if (tid < 32) sht[tid] = g_htp[b * CC_ + s * 32 + tid];
    __syncthreads();

    const float4* sp = (const float4*)(seq + ((size_t)b * CC_ + s * 32) * DD_) + tid;
    float4 acc = make_float4(0.f, 0.f, 0.f, 0.f);
    #pragma unroll
    for (int g = 0; g < 4; g++) {
        float4 v[8];
        #pragma unroll
        for (int u = 0; u < 8; u++) v[u] = sp[(g * 8 + u) * 192];   // 8 independent loads
        #pragma unroll
        for (int u = 0; u < 8; u++) {
            float wv = sht[g * 8 + u];
            acc.x += v[u].x * wv; acc.y += v[u].y * wv;
            acc.z += v[u].z * wv; acc.w += v[u].w * wv;
        }
    }
    float iv = sinv;
    acc.x *= iv; acc.y *= iv; acc.z *= iv; acc.w *= iv;
    ((float4*)(g_rsp + ((size_t)s * BB_ + b) * DD_))[tid] = acc;
}

// ================= K2r: collapse 16 rs partials -> g_rs_t [d][b] =================
// 6144 threads: b = gid/192, q = float4 index. L2-resident input.
__global__ __launch_bounds__(256) void k2r() {
    int gid = blockIdx.x * 256 + threadIdx.x;   // 24 blocks * 256 = 6144
    int b = gid / 192, q = gid - b * 192;
    const float4* src = (const float4*)(g_rsp + (size_t)b * DD_) + q;
    float4 acc = make_float4(0.f, 0.f, 0.f, 0.f);
    #pragma unroll
    for (int g = 0; g < 2; g++) {
        float4 v[8];
        #pragma unroll
        for (int u = 0; u < 8; u++) v[u] = src[(size_t)(g * 8 + u) * BB_ * DD_ / 4];
        #pragma unroll
        for (int u = 0; u < 8; u++) {
            acc.x += v[u].x; acc.y += v[u].y; acc.z += v[u].z; acc.w += v[u].w;
        }
    }
    int d = q * 4;
    g_rs_t[(d + 0) * BB_ + b] = acc.x;
    g_rs_t[(d + 1) * BB_ + b] = acc.y;
    g_rs_t[(d + 2) * BB_ + b] = acc.z;
    g_rs_t[(d + 3) * BB_ + b] = acc.w;
}

// ================= K3: dual GEMM partials (head/tail), f32x2 =================
// grid (8, 24, 2): x = n-tile(96), y = k-split(64), z = side. 128 threads tx(16)xty(8).
__global__ __launch_bounds__(128) void k3(const float* __restrict__ Wh,
                                          const float* __restrict__ Wt) {
    int nt = blockIdx.x, ks = blockIdx.y, side = blockIdx.z;
    int tid = threadIdx.x, tx = tid & 15, ty = tid >> 4;
    const float* W = side ? Wt : Wh;
    int n0 = nt * 96, kb = ks * 64;

    __shared__ float w_s[64][98];
    __shared__ unsigned long long x2_s[64][32];

    // stage W tile 64k x 96n via float2 (fully unrolled, MLP 24)
    #pragma unroll
    for (int t = 0; t < 24; t++) {
        int idx = tid + t * 128;
        int n = idx >> 5;
        int kq = idx & 31;
        float2 v = *(const float2*)(W + (size_t)(n0 + n) * KIN_ + kb + kq * 2);
        w_s[kq * 2][n] = v.x;
        w_s[kq * 2 + 1][n] = v.y;
    }
    // stage x2: coalesced reads from transposed hs/rs
    #pragma unroll
    for (int t = 0; t < 16; t++) {
        int idx = tid + t * 128;
        int kk = idx >> 5, bb = idx & 31;
        int gk = kb + kk;
        float v = (gk < 768) ? g_hs_t[gk * BB_ + bb] : g_rs_t[(gk - 768) * BB_ + bb];
        x2_s[kk][bb] = pack2(v);
    }
    __syncthreads();

    unsigned long long acc[3][4];
    #pragma unroll
    for (int i = 0; i < 3; i++)
        #pragma unroll
        for (int j = 0; j < 4; j++) acc[i][j] = 0ull;

    #pragma unroll 2
    for (int kk = 0; kk < 64; kk++) {
        unsigned long long w2[3], xb[4];
        #pragma unroll
        for (int i = 0; i < 3; i++)
            w2[i] = *(const unsigned long long*)&w_s[kk][2 * (tx + 16 * i)];
        #pragma unroll
        for (int j = 0; j < 4; j++) xb[j] = x2_s[kk][ty * 4 + j];
        #pragma unroll
        for (int i = 0; i < 3; i++)
            #pragma unroll
            for (int j = 0; j < 4; j++) acc[i][j] = ffma2(w2[i], xb[j], acc[i][j]);
    }

    unsigned long long* gp = g_gpu + ((size_t)(side * 24 + ks)) * 384 * 32;
    #pragma unroll
    for (int i = 0; i < 3; i++) {
        int P = nt * 48 + tx + 16 * i;
        #pragma unroll
        for (int j = 0; j < 4; j++)
            gp[P * 32 + ty * 4 + j] = acc[i][j];
    }
}

// ================= K3r: reduce 24 k-partials (batched MLP=8) + NER + bias + tanh =================
__global__ __launch_bounds__(256) void k3r(const float* __restrict__ Wh,
                                           const float* __restrict__ Wt,
                                           const float* __restrict__ bh,
                                           const float* __restrict__ bt,
                                           const float* __restrict__ ner) {
    int gid = blockIdx.x * 256 + threadIdx.x;
    int side = gid / 12288;
    int rem = gid - side * 12288;
    int P = rem >> 5, bb = rem & 31;
    const unsigned long long* gp = g_gpu + (size_t)side * 24 * 384 * 32 + P * 32 + bb;
    unsigned long long s = 0ull;
    #pragma unroll
    for (int g = 0; g < 3; g++) {
        unsigned long long v[8];
        #pragma unroll
        for (int u = 0; u < 8; u++) v[u] = gp[(size_t)(g * 8 + u) * 384 * 32];
        // tree add
        v[0] = addf2(v[0], v[1]); v[2] = addf2(v[2], v[3]);
        v[4] = addf2(v[4], v[5]); v[6] = addf2(v[6], v[7]);
        v[0] = addf2(v[0], v[2]); v[4] = addf2(v[4], v[6]);
        s = addf2(s, addf2(v[0], v[4]));
    }
    float2 v2 = unpack2(s);
    const float* W = side ? Wt : Wh;
    int n = 2 * P;
    float s0 = v2.x, s1 = v2.y;
    #pragma unroll
    for (int j = 0; j < 6; j++) {
        float nv = ner[bb * 12 + side * 6 + j];
        s0 += W[(size_t)n * KIN_ + KCORE_ + j] * nv;
        s1 += W[(size_t)(n + 1) * KIN_ + KCORE_ + j] * nv;
    }
    const float* bias = side ? bt : bh;
    s0 += bias[n]; s1 += bias[n + 1];
    float* dst = side ? g_tsf_t : g_hsf_t;
    dst[n * BB_ + bb] = tanhf(s0);            // transposed [n][b], coalesced
    dst[(n + 1) * BB_ + bb] = tanhf(s1);
}

// ================= K4: bilinear + logits GEMM partials, f32x2 =================
// grid (4, 24): x = n-tile(32), y = k-split. 128 threads tx(16)xty(8).
__global__ __launch_bounds__(128) void k4(const float* __restrict__ Wb) {
    int nt = blockIdx.x, ks = blockIdx.y;
    int tid = threadIdx.x, tx = tid & 15, ty = tid >> 4;
    int n0 = nt * 32;

    __shared__ float sh[32][33], st[32][33];   // [v][bb]
    __shared__ float w_s[64][34];
    __shared__ unsigned long long x2_s[64][32];

    #pragma unroll
    for (int t = 0; t < 8; t++) {
        int idx = tid + t * 128;
        int v = idx >> 5, bb = idx & 31;
        sh[v][bb] = g_hsf_t[(ks * 32 + v) * BB_ + bb];   // coalesced
        st[v][bb] = g_tsf_t[(ks * 32 + v) * BB_ + bb];
    }
    __syncthreads();

    unsigned long long acc[4] = {0ull, 0ull, 0ull, 0ull};
    for (int ch = 0; ch < 4; ch++) {
        #pragma unroll
        for (int t = 0; t < 4; t++) {
            int idx = tid + t * 128;
            int n = idx >> 4;
            int kq = idx & 15;
            int nn = n0 + n;
            float4 v = (nn < NCLS_)
                ? *(const float4*)(Wb + (size_t)nn * 6144 + ks * 256 + ch * 64 + kq * 4)
                : make_float4(0.f, 0.f, 0.f, 0.f);
            w_s[kq * 4 + 0][n] = v.x;
            w_s[kq * 4 + 1][n] = v.y;
            w_s[kq * 4 + 2][n] = v.z;
            w_s[kq * 4 + 3][n] = v.w;
        }
        #pragma unroll
        for (int t = 0; t < 16; t++) {
            int idx = tid + t * 128;
            int kk = idx >> 5, bb = idx & 31;
            int i = kk >> 3, j = kk & 7;
            x2_s[kk][bb] = pack2(sh[ch * 8 + i][bb] * st[ch * 8 + j][bb]);
        }
        __syncthreads();
        #pragma unroll 4
        for (int kk = 0; kk < 64; kk++) {
            unsigned long long w2 = *(const unsigned long long*)&w_s[kk][2 * tx];
            #pragma unroll
            for (int j = 0; j < 4; j++)
                acc[j] = ffma2(w2, x2_s[kk][ty * 4 + j], acc[j]);
        }
        __syncthreads();
    }
    int P = nt * 16 + tx;
    #pragma unroll
    for (int j = 0; j < 4; j++)
        g_lp2[((size_t)ks * 64 + P) * 32 + ty * 4 + j] = acc[j];
}

// ================= K5: final reduce + bias -> d_out =================
__global__ __launch_bounds__(256) void k5(const float* __restrict__ bbil,
                                          float* __restrict__ out) {
    int gid = blockIdx.x * 256 + threadIdx.x;
    if (gid < BB_ * NCLS_) {
        int b = gid / NCLS_, n = gid - b * NCLS_;
        int P = n >> 1, c = n & 1;
        const float* lpf = (const float*)g_lp2;
        float s = bbil[n];
        #pragma unroll
        for (int g = 0; g < 3; g++) {
            float v[8];
            #pragma unroll
            for (int u = 0; u < 8; u++)
                v[u] = lpf[((((size_t)(g * 8 + u)) * 64 + P) * 32 + b) * 2 + c];
            #pragma unroll
            for (int u = 0; u < 8; u++) s += v[u];
        }
        out[gid] = s;
    }
}

extern "C" void kernel_launch(void* const* d_in, const int* in_sizes, int n_in,
                              void* d_out, int out_size) {
    const float* seq  = (const float*)d_in[0];
    const float* att  = (const float*)d_in[1];
    const float* ner  = (const float*)d_in[2];
    const float* Wh   = (const float*)d_in[3];
    const float* bh   = (const float*)d_in[4];
    const float* Wt   = (const float*)d_in[5];
    const float* bt   = (const float*)d_in[6];
    const float* Wb   = (const float*)d_in[7];
    const float* bbil = (const float*)d_in[8];
    const int*   ep   = (const int*)d_in[9];
    float* out = (float*)d_out;

    k1<<<dim3(4, 32), 384>>>(seq, att, ep);
    k2<<<dim3(16, 32), 192>>>(seq);
    k2r<<<24, 256>>>();
    k3<<<dim3(8, 24, 2), 128>>>(Wh, Wt);
    k3r<<<96, 256>>>(Wh, Wt, bh, bt, ner);
    k4<<<dim3(4, 24), 128>>>(Wb);
    k5<<<13, 256>>>(bbil, out);
}

// round 4
// speedup vs baseline: 2.2208x; 1.0063x over previous
#include <cuda_runtime.h>

#define BB_ 32
#define HH_ 12
#define CC_ 512
#define DD_ 768
#define EMB_ 768
#define NCLS_ 97
#define KIN_ 1542
#define KCORE_ 1536

// ---------------- scratch (device globals; no allocation) ----------------
__device__ float g_hs_t[DD_ * BB_];                     // logsumexp head emb [d][b]
__device__ float g_htp[BB_ * CC_];                      // pre-normalized ht_att (b,c)
__device__ float g_htsum[BB_ * 4];                      // 4 partial sums per batch
__device__ float g_rsp[16 * BB_ * DD_];                 // rs partials [chunk][b][d]
__device__ float g_rs_t[DD_ * BB_];                     // reduced rs [d][b]
__device__ unsigned long long g_gpu[2 * 24 * 384 * 32]; // GEMM partials [side][ks][P][b]
__device__ float g_hsf_t[EMB_ * BB_];                   // tanh head features [n][b]
__device__ float g_tsf_t[EMB_ * BB_];                   // tanh tail features [n][b]
__device__ unsigned long long g_lp2[48 * 64 * 32];      // logits partials [ks][P][b]

// ---------------- f32x2 helpers ----------------
__device__ __forceinline__ unsigned long long ffma2(unsigned long long a,
                                                    unsigned long long b,
                                                    unsigned long long c) {
    unsigned long long d;
    asm("fma.rn.f32x2 %0, %1, %2, %3;" : "=l"(d) : "l"(a), "l"(b), "l"(c));
    return d;
}
__device__ __forceinline__ unsigned long long addf2(unsigned long long a,
                                                    unsigned long long b) {
    unsigned long long d;
    asm("add.rn.f32x2 %0, %1, %2;" : "=l"(d) : "l"(a), "l"(b));
    return d;
}
__device__ __forceinline__ unsigned long long pack2(float x) {
    unsigned long long r;
    asm("mov.b64 %0, {%1, %2};" : "=l"(r) : "f"(x), "f"(x));
    return r;
}
__device__ __forceinline__ float2 unpack2(unsigned long long v) {
    float2 f;
    asm("mov.b64 {%0, %1}, %2;" : "=f"(f.x), "=f"(f.y) : "l"(v));
    return f;
}

// ================= K1: hs (logsumexp) + ht_att pre + partial sums =================
__global__ __launch_bounds__(384) void k1(const float* __restrict__ seq,
                                          const float* __restrict__ att,
                                          const int* __restrict__ ep) {
    int part = blockIdx.x, b = blockIdx.y, tid = threadIdx.x;
    int w = tid >> 5, lane = tid & 31;
    __shared__ int sp0[8], sp1[8];
    __shared__ float sacc[12][128];
    __shared__ float sred[12];
    if (tid < 16) {
        int side = tid >> 3, m = tid & 7;
        int p = ep[b * 16 + side * 8 + m] + 1;  // OFFSET
        if (side) sp1[m] = p; else sp0[m] = p;
    }
    __syncthreads();

    {
        const float* ab = att + ((size_t)(b * HH_ + w)) * CC_ * CC_;
        int c4 = part * 128 + lane * 4;
        float4 v0[8], v1[8];
        #pragma unroll
        for (int m = 0; m < 8; m++) {
            v0[m] = *(const float4*)(ab + (size_t)sp0[m] * CC_ + c4);
            v1[m] = *(const float4*)(ab + (size_t)sp1[m] * CC_ + c4);
        }
        float4 a0 = make_float4(0.f, 0.f, 0.f, 0.f);
        float4 a1 = make_float4(0.f, 0.f, 0.f, 0.f);
        #pragma unroll
        for (int m = 0; m < 8; m++) {
            a0.x += v0[m].x; a0.y += v0[m].y; a0.z += v0[m].z; a0.w += v0[m].w;
            a1.x += v1[m].x; a1.y += v1[m].y; a1.z += v1[m].z; a1.w += v1[m].w;
        }
        float4 pr = make_float4(a0.x * a1.x, a0.y * a1.y, a0.z * a1.z, a0.w * a1.w);
        *(float4*)&sacc[w][lane * 4] = pr;
    }
    __syncthreads();

    float pre = 0.f;
    if (tid < 128) {
        float s = 0.f;
        #pragma unroll
        for (int h = 0; h < 12; h++) s += sacc[h][tid];
        pre = s * (1.0f / 768.0f);
        g_htp[b * CC_ + part * 128 + tid] = pre;
    }
    #pragma unroll
    for (int o = 16; o > 0; o >>= 1) pre += __shfl_xor_sync(0xffffffffu, pre, o);
    if (lane == 0) sred[w] = pre;
    __syncthreads();
    if (tid == 0) {
        float s = 0.f;
        #pragma unroll
        for (int i = 0; i < 12; i++) s += sred[i];
        g_htsum[b * 4 + part] = s;
    }

    if (part < 2) {
        int d = part * 384 + tid;
        const float* sb = seq + (size_t)b * CC_ * DD_ + d;
        float v[8];
        #pragma unroll
        for (int m = 0; m < 8; m++) v[m] = sb[(size_t)sp0[m] * DD_];
        float mx = v[0];
        #pragma unroll
        for (int m = 1; m < 8; m++) mx = fmaxf(mx, v[m]);
        float s = 0.f;
        #pragma unroll
        for (int m = 0; m < 8; m++) s += expf(v[m] - mx);
        g_hs_t[d * BB_ + b] = mx + logf(s);
    }
}

// ================= K2: rs partials (50MB streaming read), explicit MLP=8 =================
__global__ __launch_bounds__(192) void k2(const float* __restrict__ seq) {
    int s = blockIdx.x, b = blockIdx.y, tid = threadIdx.x;
    __shared__ float sht[32];
    __shared__ float sinv;
    if (tid == 0) {
        float sm = g_htsum[b * 4] + g_htsum[b * 4 + 1] + g_htsum[b * 4 + 2] + g_htsum[b * 4 + 3];
        sinv = 1.0f / (sm + 1e-5f);
    }
    if (tid < 32) sht[tid] = g_htp[b * CC_ + s * 32 + tid];
    __syncthreads();

    const float4* sp = (const float4*)(seq + ((size_t)b * CC_ + s * 32) * DD_) + tid;
    float4 acc = make_float4(0.f, 0.f, 0.f, 0.f);
    #pragma unroll
    for (int g = 0; g < 4; g++) {
        float4 v[8];
        #pragma unroll
        for (int u = 0; u < 8; u++) v[u] = sp[(g * 8 + u) * 192];
        #pragma unroll
        for (int u = 0; u < 8; u++) {
            float wv = sht[g * 8 + u];
            acc.x += v[u].x * wv; acc.y += v[u].y * wv;
            acc.z += v[u].z * wv; acc.w += v[u].w * wv;
        }
    }
    float iv = sinv;
    acc.x *= iv; acc.y *= iv; acc.z *= iv; acc.w *= iv;
    ((float4*)(g_rsp + ((size_t)s * BB_ + b) * DD_))[tid] = acc;
}

// ================= K2r: collapse 16 rs partials -> g_rs_t [d][b] =================
__global__ __launch_bounds__(256) void k2r() {
    int gid = blockIdx.x * 256 + threadIdx.x;   // 24 * 256 = 6144
    int b = gid / 192, q = gid - b * 192;
    const float4* src = (const float4*)(g_rsp + (size_t)b * DD_) + q;
    float4 acc = make_float4(0.f, 0.f, 0.f, 0.f);
    #pragma unroll
    for (int g = 0; g < 2; g++) {
        float4 v[8];
        #pragma unroll
        for (int u = 0; u < 8; u++) v[u] = src[(size_t)(g * 8 + u) * BB_ * DD_ / 4];
        #pragma unroll
        for (int u = 0; u < 8; u++) {
            acc.x += v[u].x; acc.y += v[u].y; acc.z += v[u].z; acc.w += v[u].w;
        }
    }
    int d = q * 4;
    g_rs_t[(d + 0) * BB_ + b] = acc.x;
    g_rs_t[(d + 1) * BB_ + b] = acc.y;
    g_rs_t[(d + 2) * BB_ + b] = acc.z;
    g_rs_t[(d + 3) * BB_ + b] = acc.w;
}

// ================= K3: dual GEMM partials, tile 4 n-pairs x 4 b =================
// grid (6, 24, 2): x = n-tile(128), y = k-split(64), z = side. 128 threads tx(16)xty(8).
__global__ __launch_bounds__(128) void k3(const float* __restrict__ Wh,
                                          const float* __restrict__ Wt) {
    int nt = blockIdx.x, ks = blockIdx.y, side = blockIdx.z;
    int tid = threadIdx.x, tx = tid & 15, ty = tid >> 4;
    const float* W = side ? Wt : Wh;
    int n0 = nt * 128, kb = ks * 64;

    __shared__ float w_s[64][130];                       // [kk][n]
    __shared__ unsigned long long x2_s[64][32];          // packed-dup x [kk][b]

    // stage W tile 64k x 128n via float2 (32 per thread, independent)
    #pragma unroll
    for (int t = 0; t < 32; t++) {
        int idx = tid + t * 128;          // 0..4095
        int n = idx >> 5;                 // 0..127
        int kq = idx & 31;                // kk = 2*kq
        float2 v = *(const float2*)(W + (size_t)(n0 + n) * KIN_ + kb + kq * 2);
        w_s[kq * 2][n] = v.x;
        w_s[kq * 2 + 1][n] = v.y;
    }
    // stage x2: coalesced reads from transposed hs/rs
    #pragma unroll
    for (int t = 0; t < 16; t++) {
        int idx = tid + t * 128;
        int kk = idx >> 5, bb = idx & 31;
        int gk = kb + kk;
        float v = (gk < 768) ? g_hs_t[gk * BB_ + bb] : g_rs_t[(gk - 768) * BB_ + bb];
        x2_s[kk][bb] = pack2(v);
    }
    __syncthreads();

    unsigned long long acc[4][4];
    #pragma unroll
    for (int i = 0; i < 4; i++)
        #pragma unroll
        for (int j = 0; j < 4; j++) acc[i][j] = 0ull;

    #pragma unroll 2
    for (int kk = 0; kk < 64; kk++) {
        unsigned long long w2[4], xb[4];
        #pragma unroll
        for (int i = 0; i < 4; i++)
            w2[i] = *(const unsigned long long*)&w_s[kk][2 * (tx + 16 * i)];
        #pragma unroll
        for (int j = 0; j < 4; j++) xb[j] = x2_s[kk][ty * 4 + j];
        #pragma unroll
        for (int i = 0; i < 4; i++)
            #pragma unroll
            for (int j = 0; j < 4; j++) acc[i][j] = ffma2(w2[i], xb[j], acc[i][j]);
    }

    unsigned long long* gp = g_gpu + ((size_t)(side * 24 + ks)) * 384 * 32;
    #pragma unroll
    for (int i = 0; i < 4; i++) {
        int P = nt * 64 + tx + 16 * i;    // global n-pair 0..383
        #pragma unroll
        for (int j = 0; j < 4; j++)
            gp[P * 32 + ty * 4 + j] = acc[i][j];
    }
}

// ================= K3r: reduce 24 k-partials (MLP=8 tree) + NER + bias + tanh =================
__global__ __launch_bounds__(256) void k3r(const float* __restrict__ Wh,
                                           const float* __restrict__ Wt,
                                           const float* __restrict__ bh,
                                           const float* __restrict__ bt,
                                           const float* __restrict__ ner) {
    int gid = blockIdx.x * 256 + threadIdx.x;
    int side = gid / 12288;
    int rem = gid - side * 12288;
    int P = rem >> 5, bb = rem & 31;
    const unsigned long long* gp = g_gpu + (size_t)side * 24 * 384 * 32 + P * 32 + bb;
    unsigned long long s = 0ull;
    #pragma unroll
    for (int g = 0; g < 3; g++) {
        unsigned long long v[8];
        #pragma unroll
        for (int u = 0; u < 8; u++) v[u] = gp[(size_t)(g * 8 + u) * 384 * 32];
        v[0] = addf2(v[0], v[1]); v[2] = addf2(v[2], v[3]);
        v[4] = addf2(v[4], v[5]); v[6] = addf2(v[6], v[7]);
        v[0] = addf2(v[0], v[2]); v[4] = addf2(v[4], v[6]);
        s = addf2(s, addf2(v[0], v[4]));
    }
    float2 v2 = unpack2(s);
    const float* W = side ? Wt : Wh;
    int n = 2 * P;
    float s0 = v2.x, s1 = v2.y;
    #pragma unroll
    for (int j = 0; j < 6; j++) {
        float nv = ner[bb * 12 + side * 6 + j];
        s0 += W[(size_t)n * KIN_ + KCORE_ + j] * nv;
        s1 += W[(size_t)(n + 1) * KIN_ + KCORE_ + j] * nv;
    }
    const float* bias = side ? bt : bh;
    s0 += bias[n]; s1 += bias[n + 1];
    float* dst = side ? g_tsf_t : g_hsf_t;
    dst[n * BB_ + bb] = tanhf(s0);
    dst[(n + 1) * BB_ + bb] = tanhf(s1);
}

// ================= K4: bilinear + logits GEMM partials, f32x2 =================
// grid (4, 48): x = n-tile(32), y = k-split(128 = 2 chunks of 64). 128 threads tx(16)xty(8).
__global__ __launch_bounds__(128) void k4(const float* __restrict__ Wb) {
    int nt = blockIdx.x, ks = blockIdx.y;
    int tid = threadIdx.x, tx = tid & 15, ty = tid >> 4;
    int n0 = nt * 32;

    __shared__ float sh[16][33], st[16][33];   // [v][bb]; v = local hs/ts col (16 per ks)
    __shared__ float w_s[64][34];
    __shared__ unsigned long long x2_s[64][32];

    #pragma unroll
    for (int t = 0; t < 8; t++) {
        int idx = tid + t * 128;               // 0..1023
        int half = idx >> 9;                   // 0: sh, 1: st
        int loc = idx & 511;
        int v = loc >> 5, bb = loc & 31;
        float* dstm = half ? &st[0][0] : &sh[0][0];
        const float* srcm = half ? g_tsf_t : g_hsf_t;
        dstm[v * 33 + bb] = srcm[(ks * 16 + v) * BB_ + bb];
    }
    __syncthreads();

    unsigned long long acc[4] = {0ull, 0ull, 0ull, 0ull};
    for (int ch = 0; ch < 2; ch++) {
        #pragma unroll
        for (int t = 0; t < 4; t++) {
            int idx = tid + t * 128;
            int n = idx >> 4;
            int kq = idx & 15;
            int nn = n0 + n;
            float4 v = (nn < NCLS_)
                ? *(const float4*)(Wb + (size_t)nn * 6144 + ks * 128 + ch * 64 + kq * 4)
                : make_float4(0.f, 0.f, 0.f, 0.f);
            w_s[kq * 4 + 0][n] = v.x;
            w_s[kq * 4 + 1][n] = v.y;
            w_s[kq * 4 + 2][n] = v.z;
            w_s[kq * 4 + 3][n] = v.w;
        }
        #pragma unroll
        for (int t = 0; t < 16; t++) {
            int idx = tid + t * 128;
            int kk = idx >> 5, bb = idx & 31;
            int i = kk >> 3, j = kk & 7;       // kl = ch*64+kk; g-local = ch
            x2_s[kk][bb] = pack2(sh[ch * 8 + i][bb] * st[ch * 8 + j][bb]);
        }
        __syncthreads();
        #pragma unroll 4
        for (int kk = 0; kk < 64; kk++) {
            unsigned long long w2 = *(const unsigned long long*)&w_s[kk][2 * tx];
            #pragma unroll
            for (int j = 0; j < 4; j++)
                acc[j] = ffma2(w2, x2_s[kk][ty * 4 + j], acc[j]);
        }
        __syncthreads();
    }
    int P = nt * 16 + tx;
    #pragma unroll
    for (int j = 0; j < 4; j++)
        g_lp2[((size_t)ks * 64 + P) * 32 + ty * 4 + j] = acc[j];
}

// ================= K5: final reduce + bias -> d_out =================
__global__ __launch_bounds__(256) void k5(const float* __restrict__ bbil,
                                          float* __restrict__ out) {
    int gid = blockIdx.x * 256 + threadIdx.x;
    if (gid < BB_ * NCLS_) {
        int b = gid / NCLS_, n = gid - b * NCLS_;
        int P = n >> 1, c = n & 1;
        const float* lpf = (const float*)g_lp2;
        float s = bbil[n];
        #pragma unroll
        for (int g = 0; g < 6; g++) {
            float v[8];
            #pragma unroll
            for (int u = 0; u < 8; u++)
                v[u] = lpf[((((size_t)(g * 8 + u)) * 64 + P) * 32 + b) * 2 + c];
            #pragma unroll
            for (int u = 0; u < 8; u++) s += v[u];
        }
        out[gid] = s;
    }
}

extern "C" void kernel_launch(void* const* d_in, const int* in_sizes, int n_in,
                              void* d_out, int out_size) {
    const float* seq  = (const float*)d_in[0];
    const float* att  = (const float*)d_in[1];
    const float* ner  = (const float*)d_in[2];
    const float* Wh   = (const float*)d_in[3];
    const float* bh   = (const float*)d_in[4];
    const float* Wt   = (const float*)d_in[5];
    const float* bt   = (const float*)d_in[6];
    const float* Wb   = (const float*)d_in[7];
    const float* bbil = (const float*)d_in[8];
    const int*   ep   = (const int*)d_in[9];
    float* out = (float*)d_out;

    k1<<<dim3(4, 32), 384>>>(seq, att, ep);
    k2<<<dim3(16, 32), 192>>>(seq);
    k2r<<<24, 256>>>();
    k3<<<dim3(6, 24, 2), 128>>>(Wh, Wt);
    k3r<<<96, 256>>>(Wh, Wt, bh, bt, ner);
    k4<<<dim3(4, 48), 128>>>(Wb);
    k5<<<13, 256>>>(bbil, out);
}